// round 1
// baseline (speedup 1.0000x reference)
#include <cuda_runtime.h>
#include <math.h>

#define Bsz 2
#define SEQ 2048
#define HIDN 2048
#define NH 16
#define NG 4
#define HDIM 128

static __device__ float g_Q[Bsz * SEQ * NH * HDIM];   // 32 MB
static __device__ float g_K[Bsz * SEQ * NG * HDIM];   // 8 MB
static __device__ float g_V[Bsz * SEQ * NG * HDIM];   // 8 MB
static __device__ float g_O[Bsz * SEQ * NH * HDIM];   // 32 MB

// ---------------------------------------------------------------------------
// Tiled fp32 GEMM: C[M,N] = A[M,K] @ B[K,N], all row-major.
// BM=BN=128, BK=16, 256 threads, 8x8 per-thread tile.
// M,N divisible by 128; K divisible by 16 (true for all calls here).
// ---------------------------------------------------------------------------
__global__ __launch_bounds__(256) void gemm128(
    const float* __restrict__ A, const float* __restrict__ Bm,
    float* __restrict__ C, int M, int N, int K)
{
    __shared__ float As[16][128];
    __shared__ float Bs[16][128];

    const int tid = threadIdx.x;
    const int m0 = blockIdx.y * 128;
    const int n0 = blockIdx.x * 128;
    const int tx = tid & 15;      // 0..15 -> col group
    const int ty = tid >> 4;      // 0..15 -> row group

    float acc[8][8];
#pragma unroll
    for (int i = 0; i < 8; i++)
#pragma unroll
        for (int j = 0; j < 8; j++) acc[i][j] = 0.f;

    for (int k0 = 0; k0 < K; k0 += 16) {
        // Load A tile (128 x 16) -> As transposed [k][m].  512 float4 total.
#pragma unroll
        for (int l = 0; l < 2; l++) {
            int idx = tid + l * 256;
            int r = idx >> 2;        // 0..127
            int c4 = idx & 3;        // 0..3 (x4 floats)
            float4 v = *(const float4*)&A[(size_t)(m0 + r) * K + k0 + c4 * 4];
            As[c4 * 4 + 0][r] = v.x;
            As[c4 * 4 + 1][r] = v.y;
            As[c4 * 4 + 2][r] = v.z;
            As[c4 * 4 + 3][r] = v.w;
        }
        // Load B tile (16 x 128) -> Bs[k][n].  512 float4 total.
#pragma unroll
        for (int l = 0; l < 2; l++) {
            int idx = tid + l * 256;
            int r = idx >> 5;        // 0..15
            int c4 = idx & 31;       // 0..31
            *(float4*)&Bs[r][c4 * 4] =
                *(const float4*)&Bm[(size_t)(k0 + r) * N + n0 + c4 * 4];
        }
        __syncthreads();

#pragma unroll
        for (int kk = 0; kk < 16; kk++) {
            float a[8], b[8];
            *(float4*)&a[0] = *(const float4*)&As[kk][ty * 8];
            *(float4*)&a[4] = *(const float4*)&As[kk][ty * 8 + 4];
            *(float4*)&b[0] = *(const float4*)&Bs[kk][tx * 8];
            *(float4*)&b[4] = *(const float4*)&Bs[kk][tx * 8 + 4];
#pragma unroll
            for (int i = 0; i < 8; i++)
#pragma unroll
                for (int j = 0; j < 8; j++)
                    acc[i][j] = fmaf(a[i], b[j], acc[i][j]);
        }
        __syncthreads();
    }

#pragma unroll
    for (int i = 0; i < 8; i++) {
        float4 v0, v1;
        v0.x = acc[i][0]; v0.y = acc[i][1]; v0.z = acc[i][2]; v0.w = acc[i][3];
        v1.x = acc[i][4]; v1.y = acc[i][5]; v1.z = acc[i][6]; v1.w = acc[i][7];
        float* cp = &C[(size_t)(m0 + ty * 8 + i) * N + n0 + tx * 8];
        *(float4*)&cp[0] = v0;
        *(float4*)&cp[4] = v1;
    }
}

// ---------------------------------------------------------------------------
// RoPE (half-rotation convention), applied in place.
// t layout: [B*S, nheads, 128].  One thread per (row, head, d<64) pair.
// ---------------------------------------------------------------------------
__global__ void rope_kernel(float* __restrict__ t,
                            const float* __restrict__ cosp,
                            const float* __restrict__ sinp, int nheads)
{
    int idx = blockIdx.x * blockDim.x + threadIdx.x;
    int d = idx & 63;
    int h = (idx >> 6) % nheads;
    int row = idx / (64 * nheads);      // b*S + s
    int pos = row & (SEQ - 1);

    float c0 = cosp[pos * HDIM + d];
    float s0 = sinp[pos * HDIM + d];
    float c1 = cosp[pos * HDIM + d + 64];
    float s1 = sinp[pos * HDIM + d + 64];

    float* p = t + ((size_t)row * nheads + h) * HDIM;
    float q0 = p[d];
    float q1 = p[d + 64];
    p[d]      = q0 * c0 - q1 * s0;
    p[d + 64] = q1 * c1 + q0 * s1;
}

// ---------------------------------------------------------------------------
// Causal flash attention, fp32.
// Grid: (S/64, H, B).  256 threads.  BM=BN=64, D=128.
// Dyn smem: Qs[64][132] + KVs[64][132] + Ss[64][68] + m[64] + l[64]
// ---------------------------------------------------------------------------
#define QSTR 132
#define SSTR 68
#define FA_SMEM_FLOATS (64 * QSTR * 2 + 64 * SSTR + 128)
#define FA_SMEM_BYTES (FA_SMEM_FLOATS * 4)

__global__ __launch_bounds__(256) void flash_attn(
    const float* __restrict__ Q, const float* __restrict__ K,
    const float* __restrict__ V, float* __restrict__ O)
{
    extern __shared__ float sm[];
    float* Qs = sm;
    float* KVs = Qs + 64 * QSTR;
    float* Ss = KVs + 64 * QSTR;
    float* mrow = Ss + 64 * SSTR;
    float* lrow = mrow + 64;

    const float SCALE = 0.088388347648318447f;  // 1/sqrt(128)
    const int tid = threadIdx.x;
    const int qb = blockIdx.x, h = blockIdx.y, b = blockIdx.z;
    const int g = h >> 2;                 // H/G = 4
    const int q0 = qb * 64;

    // Load Q tile: 64 rows x 128 floats = 2048 float4, 8 per thread.
#pragma unroll
    for (int l = 0; l < 8; l++) {
        int idx = tid + l * 256;
        int r = idx >> 5, c4 = idx & 31;
        *(float4*)&Qs[r * QSTR + c4 * 4] =
            *(const float4*)&Q[((size_t)(b * SEQ + q0 + r)) * (NH * HDIM) + h * HDIM + c4 * 4];
    }
    if (tid < 64) { mrow[tid] = -1e30f; lrow[tid] = 0.f; }

    float acc[32];
#pragma unroll
    for (int i = 0; i < 32; i++) acc[i] = 0.f;

    const int rr = tid >> 2;        // row owned for softmax / PV
    const int l4 = tid & 3;
    const int d0 = l4 * 32;
    const int tx = tid & 15;        // S-tile col group
    const int ty = tid >> 4;        // S-tile row group
    __syncthreads();

    for (int kt = 0; kt <= qb; kt++) {
        const int k0 = kt * 64;
        // Load K tile into KVs
#pragma unroll
        for (int l = 0; l < 8; l++) {
            int idx = tid + l * 256;
            int r = idx >> 5, c4 = idx & 31;
            *(float4*)&KVs[r * QSTR + c4 * 4] =
                *(const float4*)&K[((size_t)(b * SEQ + k0 + r)) * (NG * HDIM) + g * HDIM + c4 * 4];
        }
        __syncthreads();

        // S = Q K^T : each thread computes 4x4 of the 64x64 tile
        float sacc[4][4];
#pragma unroll
        for (int i = 0; i < 4; i++)
#pragma unroll
            for (int j = 0; j < 4; j++) sacc[i][j] = 0.f;

        for (int k4 = 0; k4 < 32; k4++) {
            float4 a[4], bb[4];
#pragma unroll
            for (int i = 0; i < 4; i++)
                a[i] = *(const float4*)&Qs[(4 * ty + i) * QSTR + k4 * 4];
#pragma unroll
            for (int j = 0; j < 4; j++)
                bb[j] = *(const float4*)&KVs[(4 * tx + j) * QSTR + k4 * 4];
#pragma unroll
            for (int i = 0; i < 4; i++)
#pragma unroll
                for (int j = 0; j < 4; j++)
                    sacc[i][j] += a[i].x * bb[j].x + a[i].y * bb[j].y +
                                  a[i].z * bb[j].z + a[i].w * bb[j].w;
        }

        const bool diag = (kt == qb);
#pragma unroll
        for (int i = 0; i < 4; i++)
#pragma unroll
            for (int j = 0; j < 4; j++) {
                int rq = 4 * ty + i, ck = 4 * tx + j;
                float sv = sacc[i][j] * SCALE;
                if (diag && (k0 + ck > q0 + rq)) sv = -1e30f;
                Ss[rq * SSTR + ck] = sv;
            }
        __syncthreads();

        // Online softmax: 4 threads per row, 16 cols each.
        float lmax = -1e30f;
#pragma unroll
        for (int c = 0; c < 16; c++)
            lmax = fmaxf(lmax, Ss[rr * SSTR + l4 * 16 + c]);
        lmax = fmaxf(lmax, __shfl_xor_sync(0xffffffffu, lmax, 1));
        lmax = fmaxf(lmax, __shfl_xor_sync(0xffffffffu, lmax, 2));
        float mo = mrow[rr];
        float mn = fmaxf(mo, lmax);
        float ls = 0.f;
#pragma unroll
        for (int c = 0; c < 16; c++) {
            int cc = rr * SSTR + l4 * 16 + c;
            float p = __expf(Ss[cc] - mn);
            Ss[cc] = p;
            ls += p;
        }
        ls += __shfl_xor_sync(0xffffffffu, ls, 1);
        ls += __shfl_xor_sync(0xffffffffu, ls, 2);
        float cf = __expf(mo - mn);
        if (l4 == 0) { mrow[rr] = mn; lrow[rr] = lrow[rr] * cf + ls; }

        // Load V tile over KVs (K no longer needed past the sync above)
#pragma unroll
        for (int l = 0; l < 8; l++) {
            int idx = tid + l * 256;
            int r = idx >> 5, c4 = idx & 31;
            *(float4*)&KVs[r * QSTR + c4 * 4] =
                *(const float4*)&V[((size_t)(b * SEQ + k0 + r)) * (NG * HDIM) + g * HDIM + c4 * 4];
        }
        __syncthreads();

        // O += P @ V : thread owns row rr, cols [d0, d0+32)
#pragma unroll
        for (int i = 0; i < 32; i++) acc[i] *= cf;
        for (int c = 0; c < 64; c++) {
            float p = Ss[rr * SSTR + c];
            const float* vp = &KVs[c * QSTR + d0];
#pragma unroll
            for (int i8 = 0; i8 < 8; i8++) {
                float4 v = *(const float4*)&vp[i8 * 4];
                acc[i8 * 4 + 0] = fmaf(p, v.x, acc[i8 * 4 + 0]);
                acc[i8 * 4 + 1] = fmaf(p, v.y, acc[i8 * 4 + 1]);
                acc[i8 * 4 + 2] = fmaf(p, v.z, acc[i8 * 4 + 2]);
                acc[i8 * 4 + 3] = fmaf(p, v.w, acc[i8 * 4 + 3]);
            }
        }
        __syncthreads();
    }

    float linv = 1.f / lrow[rr];
#pragma unroll
    for (int i8 = 0; i8 < 8; i8++) {
        float4 v;
        v.x = acc[i8 * 4 + 0] * linv;
        v.y = acc[i8 * 4 + 1] * linv;
        v.z = acc[i8 * 4 + 2] * linv;
        v.w = acc[i8 * 4 + 3] * linv;
        *(float4*)&O[((size_t)(b * SEQ + q0 + rr)) * (NH * HDIM) + h * HDIM + d0 + i8 * 4] = v;
    }
}

// ---------------------------------------------------------------------------
extern "C" void kernel_launch(void* const* d_in, const int* in_sizes, int n_in,
                              void* d_out, int out_size)
{
    const float* x    = (const float*)d_in[0];
    const float* cosp = (const float*)d_in[1];
    const float* sinp = (const float*)d_in[2];
    const float* Wq   = (const float*)d_in[3];
    const float* Wk   = (const float*)d_in[4];
    const float* Wv   = (const float*)d_in[5];
    const float* Wo   = (const float*)d_in[6];
    float* out = (float*)d_out;

    float *Qb, *Kb, *Vb, *Ob;
    cudaGetSymbolAddress((void**)&Qb, g_Q);
    cudaGetSymbolAddress((void**)&Kb, g_K);
    cudaGetSymbolAddress((void**)&Vb, g_V);
    cudaGetSymbolAddress((void**)&Ob, g_O);

    const int M = Bsz * SEQ;   // 4096

    // QKV projections
    gemm128<<<dim3((NH * HDIM) / 128, M / 128), 256>>>(x, Wq, Qb, M, NH * HDIM, HIDN);
    gemm128<<<dim3((NG * HDIM) / 128, M / 128), 256>>>(x, Wk, Kb, M, NG * HDIM, HIDN);
    gemm128<<<dim3((NG * HDIM) / 128, M / 128), 256>>>(x, Wv, Vb, M, NG * HDIM, HIDN);

    // RoPE on Q and K
    rope_kernel<<<(M * NH * 64) / 256, 256>>>(Qb, cosp, sinp, NH);
    rope_kernel<<<(M * NG * 64) / 256, 256>>>(Kb, cosp, sinp, NG);

    // Causal flash attention
    cudaFuncSetAttribute(flash_attn, cudaFuncAttributeMaxDynamicSharedMemorySize,
                         FA_SMEM_BYTES);
    flash_attn<<<dim3(SEQ / 64, NH, Bsz), 256, FA_SMEM_BYTES>>>(Qb, Kb, Vb, Ob);

    // Output projection
    gemm128<<<dim3(HIDN / 128, M / 128), 256>>>(Ob, Wo, out, M, HIDN, HIDN);
}

// round 3
// speedup vs baseline: 1.0698x; 1.0698x over previous
#include <cuda_runtime.h>
#include <math.h>
#include <stdint.h>

#define Bsz 2
#define SEQ 2048
#define HIDN 2048
#define NH 16
#define NG 4
#define HDIM 128

static __device__ float g_Q[Bsz * SEQ * NH * HDIM];   // 32 MB
static __device__ float g_K[Bsz * SEQ * NG * HDIM];   // 8 MB
static __device__ float g_V[Bsz * SEQ * NG * HDIM];   // 8 MB
static __device__ float g_O[Bsz * SEQ * NH * HDIM];   // 32 MB

__device__ __forceinline__ uint32_t smem_u32(const void* p) {
    return (uint32_t)__cvta_generic_to_shared(p);
}

__device__ __forceinline__ uint32_t f2tf32(float v) {
    uint32_t r;
    asm("cvt.rna.tf32.f32 %0, %1;\n" : "=r"(r) : "f"(v));
    return r;
}
// split v into tf32 hi + tf32 lo (3xTF32 compensation)
__device__ __forceinline__ void tf32_split(float v, uint32_t& hi, uint32_t& lo) {
    hi = f2tf32(v);
    lo = f2tf32(v - __uint_as_float(hi));
}

#define CP_ASYNC16(dst_u32, src_ptr) \
    asm volatile("cp.async.cg.shared.global [%0], [%1], 16;\n" \
                 :: "r"(dst_u32), "l"(src_ptr))

#define MMA_TF32(d, a0, a1, a2, a3, b0, b1) \
    asm volatile( \
        "mma.sync.aligned.m16n8k8.row.col.f32.tf32.tf32.f32 " \
        "{%0,%1,%2,%3},{%4,%5,%6,%7},{%8,%9},{%0,%1,%2,%3};\n" \
        : "+f"(d[0]), "+f"(d[1]), "+f"(d[2]), "+f"(d[3]) \
        : "r"(a0), "r"(a1), "r"(a2), "r"(a3), "r"(b0), "r"(b1))

// ---------------------------------------------------------------------------
// 3xTF32 tensor-core GEMM: C[M,N] = A[M,K] @ B[K,N], row-major fp32 in/out.
// BM=BN=128, BK=32, 256 threads (8 warps, each 64x32 via m16n8k8).
// Each logical MMA done as 3 tf32 MMAs (hi/lo error compensation) ->
// fp32-equivalent accuracy. Double-buffered cp.async.
// ---------------------------------------------------------------------------
#define GBM 128
#define GBN 128
#define GBK 32
#define ASTR 36    // bank map: row*4+col -> conflict-free
#define BSTR 136   // bank map: k*8+col  -> conflict-free
#define GEMM_SMEM_BYTES ((2 * GBM * ASTR + 2 * GBK * BSTR) * 4)

__global__ __launch_bounds__(256) void gemm_tf32x3(
    const float* __restrict__ A, const float* __restrict__ B,
    float* __restrict__ C, int M, int N, int K)
{
    extern __shared__ float sh[];
    float* As = sh;                      // 2 x [128][36]
    float* Bs = sh + 2 * GBM * ASTR;     // 2 x [32][136]

    const int tid = threadIdx.x;
    const int lane = tid & 31;
    const int w = tid >> 5;
    const int wm = (w >> 2) * 64;        // warp row offset in tile
    const int wn = (w & 3) * 32;         // warp col offset in tile
    const int m0 = blockIdx.y * GBM;
    const int n0 = blockIdx.x * GBN;

    float acc[4][4][4];                  // [mf][nf][reg]
#pragma unroll
    for (int i = 0; i < 4; i++)
#pragma unroll
        for (int j = 0; j < 4; j++)
#pragma unroll
            for (int r = 0; r < 4; r++) acc[i][j][r] = 0.f;

    const int NT = K / GBK;

    auto load_tile = [&](int kt, int buf) {
        float* ad = As + buf * GBM * ASTR;
        const float* asrc = A + (size_t)m0 * K + kt * GBK;
#pragma unroll
        for (int l = 0; l < 4; l++) {
            int c = tid + l * 256;
            int r = c >> 3, c4 = c & 7;          // 128 rows x 8 float4
            CP_ASYNC16(smem_u32(ad + r * ASTR + c4 * 4),
                       asrc + (size_t)r * K + c4 * 4);
        }
        float* bd = Bs + buf * GBK * BSTR;
        const float* bsrc = B + (size_t)(kt * GBK) * N + n0;
#pragma unroll
        for (int l = 0; l < 4; l++) {
            int c = tid + l * 256;
            int r = c >> 5, c4 = c & 31;         // 32 rows x 32 float4
            CP_ASYNC16(smem_u32(bd + r * BSTR + c4 * 4),
                       bsrc + (size_t)r * N + c4 * 4);
        }
    };

    load_tile(0, 0);
    asm volatile("cp.async.commit_group;\n" ::: "memory");

    for (int kt = 0; kt < NT; kt++) {
        if (kt + 1 < NT) {
            load_tile(kt + 1, (kt + 1) & 1);
            asm volatile("cp.async.commit_group;\n" ::: "memory");
            asm volatile("cp.async.wait_group 1;\n" ::: "memory");
        } else {
            asm volatile("cp.async.wait_group 0;\n" ::: "memory");
        }
        __syncthreads();

        const float* Ab = As + (kt & 1) * GBM * ASTR;
        const float* Bb = Bs + (kt & 1) * GBK * BSTR;

#pragma unroll
        for (int kk = 0; kk < GBK; kk += 8) {
            uint32_t ahi[4][4], alo[4][4];
            const int kb = kk + (lane & 3);
#pragma unroll
            for (int mf = 0; mf < 4; mf++) {
                int row = wm + mf * 16 + (lane >> 2);
                tf32_split(Ab[row * ASTR + kb],           ahi[mf][0], alo[mf][0]);
                tf32_split(Ab[(row + 8) * ASTR + kb],     ahi[mf][1], alo[mf][1]);
                tf32_split(Ab[row * ASTR + kb + 4],       ahi[mf][2], alo[mf][2]);
                tf32_split(Ab[(row + 8) * ASTR + kb + 4], ahi[mf][3], alo[mf][3]);
            }
#pragma unroll
            for (int nf = 0; nf < 4; nf++) {
                int col = wn + nf * 8 + (lane >> 2);
                uint32_t b0h, b0l, b1h, b1l;
                tf32_split(Bb[kb * BSTR + col],       b0h, b0l);
                tf32_split(Bb[(kb + 4) * BSTR + col], b1h, b1l);
#pragma unroll
                for (int mf = 0; mf < 4; mf++) {
                    // small terms first, then the big one (CUTLASS order)
                    MMA_TF32(acc[mf][nf],
                             alo[mf][0], alo[mf][1], alo[mf][2], alo[mf][3],
                             b0h, b1h);
                    MMA_TF32(acc[mf][nf],
                             ahi[mf][0], ahi[mf][1], ahi[mf][2], ahi[mf][3],
                             b0l, b1l);
                    MMA_TF32(acc[mf][nf],
                             ahi[mf][0], ahi[mf][1], ahi[mf][2], ahi[mf][3],
                             b0h, b1h);
                }
            }
        }
        __syncthreads();
    }

    // Epilogue
#pragma unroll
    for (int mf = 0; mf < 4; mf++) {
#pragma unroll
        for (int nf = 0; nf < 4; nf++) {
            int row = m0 + wm + mf * 16 + (lane >> 2);
            int col = n0 + wn + nf * 8 + (lane & 3) * 2;
            float2 v0 = make_float2(acc[mf][nf][0], acc[mf][nf][1]);
            float2 v1 = make_float2(acc[mf][nf][2], acc[mf][nf][3]);
            *(float2*)&C[(size_t)row * N + col] = v0;
            *(float2*)&C[(size_t)(row + 8) * N + col] = v1;
        }
    }
}

// ---------------------------------------------------------------------------
// RoPE (half-rotation convention), applied in place.
// ---------------------------------------------------------------------------
__global__ void rope_kernel(float* __restrict__ t,
                            const float* __restrict__ cosp,
                            const float* __restrict__ sinp, int nheads)
{
    int idx = blockIdx.x * blockDim.x + threadIdx.x;
    int d = idx & 63;
    int h = (idx >> 6) % nheads;
    int row = idx / (64 * nheads);      // b*S + s
    int pos = row & (SEQ - 1);

    float c0 = cosp[pos * HDIM + d];
    float s0 = sinp[pos * HDIM + d];
    float c1 = cosp[pos * HDIM + d + 64];
    float s1 = sinp[pos * HDIM + d + 64];

    float* p = t + ((size_t)row * nheads + h) * HDIM;
    float q0 = p[d];
    float q1 = p[d + 64];
    p[d]      = q0 * c0 - q1 * s0;
    p[d + 64] = q1 * c1 + q0 * s1;
}

// ---------------------------------------------------------------------------
// Causal flash attention, fp32 SIMT (unchanged).
// ---------------------------------------------------------------------------
#define QSTR 132
#define SSTR 68
#define FA_SMEM_FLOATS (64 * QSTR * 2 + 64 * SSTR + 128)
#define FA_SMEM_BYTES (FA_SMEM_FLOATS * 4)

__global__ __launch_bounds__(256) void flash_attn(
    const float* __restrict__ Q, const float* __restrict__ K,
    const float* __restrict__ V, float* __restrict__ O)
{
    extern __shared__ float sm[];
    float* Qs = sm;
    float* KVs = Qs + 64 * QSTR;
    float* Ss = KVs + 64 * QSTR;
    float* mrow = Ss + 64 * SSTR;
    float* lrow = mrow + 64;

    const float SCALE = 0.088388347648318447f;  // 1/sqrt(128)
    const int tid = threadIdx.x;
    const int qb = blockIdx.x, h = blockIdx.y, b = blockIdx.z;
    const int g = h >> 2;                 // H/G = 4
    const int q0 = qb * 64;

#pragma unroll
    for (int l = 0; l < 8; l++) {
        int idx = tid + l * 256;
        int r = idx >> 5, c4 = idx & 31;
        *(float4*)&Qs[r * QSTR + c4 * 4] =
            *(const float4*)&Q[((size_t)(b * SEQ + q0 + r)) * (NH * HDIM) + h * HDIM + c4 * 4];
    }
    if (tid < 64) { mrow[tid] = -1e30f; lrow[tid] = 0.f; }

    float acc[32];
#pragma unroll
    for (int i = 0; i < 32; i++) acc[i] = 0.f;

    const int rr = tid >> 2;
    const int l4 = tid & 3;
    const int d0 = l4 * 32;
    const int tx = tid & 15;
    const int ty = tid >> 4;
    __syncthreads();

    for (int kt = 0; kt <= qb; kt++) {
        const int k0 = kt * 64;
#pragma unroll
        for (int l = 0; l < 8; l++) {
            int idx = tid + l * 256;
            int r = idx >> 5, c4 = idx & 31;
            *(float4*)&KVs[r * QSTR + c4 * 4] =
                *(const float4*)&K[((size_t)(b * SEQ + k0 + r)) * (NG * HDIM) + g * HDIM + c4 * 4];
        }
        __syncthreads();

        float sacc[4][4];
#pragma unroll
        for (int i = 0; i < 4; i++)
#pragma unroll
            for (int j = 0; j < 4; j++) sacc[i][j] = 0.f;

        for (int k4 = 0; k4 < 32; k4++) {
            float4 a[4], bb[4];
#pragma unroll
            for (int i = 0; i < 4; i++)
                a[i] = *(const float4*)&Qs[(4 * ty + i) * QSTR + k4 * 4];
#pragma unroll
            for (int j = 0; j < 4; j++)
                bb[j] = *(const float4*)&KVs[(4 * tx + j) * QSTR + k4 * 4];
#pragma unroll
            for (int i = 0; i < 4; i++)
#pragma unroll
                for (int j = 0; j < 4; j++)
                    sacc[i][j] += a[i].x * bb[j].x + a[i].y * bb[j].y +
                                  a[i].z * bb[j].z + a[i].w * bb[j].w;
        }

        const bool diag = (kt == qb);
#pragma unroll
        for (int i = 0; i < 4; i++)
#pragma unroll
            for (int j = 0; j < 4; j++) {
                int rq = 4 * ty + i, ck = 4 * tx + j;
                float sv = sacc[i][j] * SCALE;
                if (diag && (k0 + ck > q0 + rq)) sv = -1e30f;
                Ss[rq * SSTR + ck] = sv;
            }
        __syncthreads();

        float lmax = -1e30f;
#pragma unroll
        for (int c = 0; c < 16; c++)
            lmax = fmaxf(lmax, Ss[rr * SSTR + l4 * 16 + c]);
        lmax = fmaxf(lmax, __shfl_xor_sync(0xffffffffu, lmax, 1));
        lmax = fmaxf(lmax, __shfl_xor_sync(0xffffffffu, lmax, 2));
        float mo = mrow[rr];
        float mn = fmaxf(mo, lmax);
        float ls = 0.f;
#pragma unroll
        for (int c = 0; c < 16; c++) {
            int cc = rr * SSTR + l4 * 16 + c;
            float p = __expf(Ss[cc] - mn);
            Ss[cc] = p;
            ls += p;
        }
        ls += __shfl_xor_sync(0xffffffffu, ls, 1);
        ls += __shfl_xor_sync(0xffffffffu, ls, 2);
        float cf = __expf(mo - mn);
        if (l4 == 0) { mrow[rr] = mn; lrow[rr] = lrow[rr] * cf + ls; }

#pragma unroll
        for (int l = 0; l < 8; l++) {
            int idx = tid + l * 256;
            int r = idx >> 5, c4 = idx & 31;
            *(float4*)&KVs[r * QSTR + c4 * 4] =
                *(const float4*)&V[((size_t)(b * SEQ + k0 + r)) * (NG * HDIM) + g * HDIM + c4 * 4];
        }
        __syncthreads();

#pragma unroll
        for (int i = 0; i < 32; i++) acc[i] *= cf;
        for (int c = 0; c < 64; c++) {
            float p = Ss[rr * SSTR + c];
            const float* vp = &KVs[c * QSTR + d0];
#pragma unroll
            for (int i8 = 0; i8 < 8; i8++) {
                float4 v = *(const float4*)&vp[i8 * 4];
                acc[i8 * 4 + 0] = fmaf(p, v.x, acc[i8 * 4 + 0]);
                acc[i8 * 4 + 1] = fmaf(p, v.y, acc[i8 * 4 + 1]);
                acc[i8 * 4 + 2] = fmaf(p, v.z, acc[i8 * 4 + 2]);
                acc[i8 * 4 + 3] = fmaf(p, v.w, acc[i8 * 4 + 3]);
            }
        }
        __syncthreads();
    }

    float linv = 1.f / lrow[rr];
#pragma unroll
    for (int i8 = 0; i8 < 8; i8++) {
        float4 v;
        v.x = acc[i8 * 4 + 0] * linv;
        v.y = acc[i8 * 4 + 1] * linv;
        v.z = acc[i8 * 4 + 2] * linv;
        v.w = acc[i8 * 4 + 3] * linv;
        *(float4*)&O[((size_t)(b * SEQ + q0 + rr)) * (NH * HDIM) + h * HDIM + d0 + i8 * 4] = v;
    }
}

// ---------------------------------------------------------------------------
extern "C" void kernel_launch(void* const* d_in, const int* in_sizes, int n_in,
                              void* d_out, int out_size)
{
    const float* x    = (const float*)d_in[0];
    const float* cosp = (const float*)d_in[1];
    const float* sinp = (const float*)d_in[2];
    const float* Wq   = (const float*)d_in[3];
    const float* Wk   = (const float*)d_in[4];
    const float* Wv   = (const float*)d_in[5];
    const float* Wo   = (const float*)d_in[6];
    float* out = (float*)d_out;

    float *Qb, *Kb, *Vb, *Ob;
    cudaGetSymbolAddress((void**)&Qb, g_Q);
    cudaGetSymbolAddress((void**)&Kb, g_K);
    cudaGetSymbolAddress((void**)&Vb, g_V);
    cudaGetSymbolAddress((void**)&Ob, g_O);

    const int M = Bsz * SEQ;   // 4096

    cudaFuncSetAttribute(gemm_tf32x3, cudaFuncAttributeMaxDynamicSharedMemorySize,
                         GEMM_SMEM_BYTES);

    // QKV projections (3xTF32 tensor cores)
    gemm_tf32x3<<<dim3((NH * HDIM) / 128, M / 128), 256, GEMM_SMEM_BYTES>>>(
        x, Wq, Qb, M, NH * HDIM, HIDN);
    gemm_tf32x3<<<dim3((NG * HDIM) / 128, M / 128), 256, GEMM_SMEM_BYTES>>>(
        x, Wk, Kb, M, NG * HDIM, HIDN);
    gemm_tf32x3<<<dim3((NG * HDIM) / 128, M / 128), 256, GEMM_SMEM_BYTES>>>(
        x, Wv, Vb, M, NG * HDIM, HIDN);

    // RoPE on Q and K
    rope_kernel<<<(M * NH * 64) / 256, 256>>>(Qb, cosp, sinp, NH);
    rope_kernel<<<(M * NG * 64) / 256, 256>>>(Kb, cosp, sinp, NG);

    // Causal flash attention (fp32 SIMT)
    cudaFuncSetAttribute(flash_attn, cudaFuncAttributeMaxDynamicSharedMemorySize,
                         FA_SMEM_BYTES);
    flash_attn<<<dim3(SEQ / 64, NH, Bsz), 256, FA_SMEM_BYTES>>>(Qb, Kb, Vb, Ob);

    // Output projection (3xTF32 tensor cores)
    gemm_tf32x3<<<dim3(HIDN / 128, M / 128), 256, GEMM_SMEM_BYTES>>>(
        Ob, Wo, out, M, HIDN, HIDN);
}